// round 6
// baseline (speedup 1.0000x reference)
#include <cuda_runtime.h>

#define BB   2
#define TT   2048
#define DD   1024
#define HH   16
#define HDIM 64
#define MM   (BB*TT)       // 4096
#define NQ   (HH*HDIM)     // 1024
#define SZ   (BB*HH*TT*HDIM)  // 4,194,304

// One scratch array: [0]=q, [1]=k, [2]=v, [3]=attention output
__device__ __align__(256) float g_scratch[4ull * SZ];

// Clamped global accessors (diagnostic: OOB becomes wrong value, not fault)
__device__ __forceinline__ float gld(const float* __restrict__ p,
                                     unsigned long long i, unsigned long long n) {
    if (i >= n) i = n - 1;
    return p[i];
}
__device__ __forceinline__ void gst(float* __restrict__ p,
                                    unsigned long long i, unsigned long long n, float v) {
    if (i >= n) i = n - 1;
    p[i] = v;
}

// ---------------------------------------------------------------------------
// QKV projection: out[b,h,t,hd] = sum_d x[b,t,d] * W[h,d,hd]
// Grid (32, 8, 3): z selects Wq/Wk/Wv and scratch slot.
// 128x128x16 tiles, 256 threads, strided 8x8 micro-tile (rows tm+16i, cols tn+16j).
// All scalar loads/stores.
// ---------------------------------------------------------------------------
__global__ __launch_bounds__(256)
void qkv_proj_kernel(const float* __restrict__ x,
                     const float* __restrict__ Wq,
                     const float* __restrict__ Wk,
                     const float* __restrict__ Wv) {
    __shared__ float As[16][129];   // [k][m]  pad 129 -> conflict-free
    __shared__ float Bs[16][128];   // [k][n]  128 ok for strided reads
    const float* W  = (blockIdx.z == 0) ? Wq : (blockIdx.z == 1) ? Wk : Wv;
    float* out = g_scratch + (size_t)blockIdx.z * SZ;

    const int bm  = blockIdx.x * 128;
    const int bn  = blockIdx.y * 128;
    const int tid = threadIdx.x;
    const int tm  = tid >> 4;    // 0..15
    const int tn  = tid & 15;    // 0..15

    float acc[8][8];
#pragma unroll
    for (int i = 0; i < 8; i++)
#pragma unroll
        for (int j = 0; j < 8; j++) acc[i][j] = 0.f;

    for (int k0 = 0; k0 < DD; k0 += 16) {
#pragma unroll
        for (int it = 0; it < 8; it++) {
            int idx = tid + it * 256;         // 0..2047
            int rowA = idx >> 4, kkA = idx & 15;
            As[kkA][rowA] = gld(x,
                (unsigned long long)(bm + rowA) * DD + (k0 + kkA),
                (unsigned long long)MM * DD);
            int kkB = idx >> 7, nnB = idx & 127;
            int n = bn + nnB;
            Bs[kkB][nnB] = gld(W,
                ((unsigned long long)(n >> 6) * DD + (k0 + kkB)) * HDIM + (n & 63),
                (unsigned long long)HH * DD * HDIM);
        }
        __syncthreads();
#pragma unroll
        for (int kk = 0; kk < 16; kk++) {
            float ar[8], br[8];
#pragma unroll
            for (int i = 0; i < 8; i++) ar[i] = As[kk][tm + 16 * i];
#pragma unroll
            for (int j = 0; j < 8; j++) br[j] = Bs[kk][tn + 16 * j];
#pragma unroll
            for (int i = 0; i < 8; i++)
#pragma unroll
                for (int j = 0; j < 8; j++) acc[i][j] += ar[i] * br[j];
        }
        __syncthreads();
    }
    // Write out to scratch in [B,H,T,HD]
#pragma unroll
    for (int i = 0; i < 8; i++) {
        int m = bm + tm + 16 * i;
        int b = m >> 11, t = m & 2047;
#pragma unroll
        for (int j = 0; j < 8; j++) {
            int n = bn + tn + 16 * j;
            gst(out,
                (((unsigned long long)b * HH + (n >> 6)) * TT + t) * HDIM + (n & 63),
                (unsigned long long)SZ, acc[i][j]);
        }
    }
}

// ---------------------------------------------------------------------------
// Output projection: out[m,n] = sum_d A[m,d]*Wo[d,n] + bo[n]
// ---------------------------------------------------------------------------
__global__ __launch_bounds__(256)
void out_proj_kernel(const float* __restrict__ Wo,
                     const float* __restrict__ bo,
                     float* __restrict__ out) {
    __shared__ float As[16][129];
    __shared__ float Bs[16][128];
    const float* A = g_scratch + 3ull * SZ;

    const int bm  = blockIdx.x * 128;
    const int bn  = blockIdx.y * 128;
    const int tid = threadIdx.x;
    const int tm  = tid >> 4;
    const int tn  = tid & 15;

    float acc[8][8];
#pragma unroll
    for (int i = 0; i < 8; i++)
#pragma unroll
        for (int j = 0; j < 8; j++) acc[i][j] = 0.f;

    for (int k0 = 0; k0 < DD; k0 += 16) {
#pragma unroll
        for (int it = 0; it < 8; it++) {
            int idx = tid + it * 256;
            int rowA = idx >> 4, kkA = idx & 15;
            As[kkA][rowA] = gld(A,
                (unsigned long long)(bm + rowA) * DD + (k0 + kkA),
                (unsigned long long)MM * DD);
            int kkB = idx >> 7, nnB = idx & 127;
            Bs[kkB][nnB] = gld(Wo,
                (unsigned long long)(k0 + kkB) * DD + (bn + nnB),
                (unsigned long long)DD * DD);
        }
        __syncthreads();
#pragma unroll
        for (int kk = 0; kk < 16; kk++) {
            float ar[8], br[8];
#pragma unroll
            for (int i = 0; i < 8; i++) ar[i] = As[kk][tm + 16 * i];
#pragma unroll
            for (int j = 0; j < 8; j++) br[j] = Bs[kk][tn + 16 * j];
#pragma unroll
            for (int i = 0; i < 8; i++)
#pragma unroll
                for (int j = 0; j < 8; j++) acc[i][j] += ar[i] * br[j];
        }
        __syncthreads();
    }
#pragma unroll
    for (int i = 0; i < 8; i++) {
        int m = bm + tm + 16 * i;
#pragma unroll
        for (int j = 0; j < 8; j++) {
            int n = bn + tn + 16 * j;
            float bias = gld(bo, (unsigned long long)n, DD);
            gst(out, (unsigned long long)m * DD + n,
                (unsigned long long)MM * DD, acc[i][j] + bias);
        }
    }
}

// ---------------------------------------------------------------------------
// Flash attention (causal), fp32, online softmax. Warp-centric, static smem
// ~29KB, all-scalar loads. Grid: (B*H, T/32). Block: 256 threads = 8 warps.
// Warp w owns query rows w*4..w*4+3. Key tiles of 32 (kt <= qt).
// ---------------------------------------------------------------------------
__global__ __launch_bounds__(256)
void attn_kernel() {
    __shared__ float Qs[32][65];
    __shared__ float Ks[32][65];
    __shared__ float Vs[32][66];
    __shared__ float Ps[32][33];

    const int bh = blockIdx.x;       // b*H + h
    const int qt = blockIdx.y;       // query tile (32 rows)
    const int bb = bh >> 4;
    const int h  = bh & 15;
    const unsigned long long base = (unsigned long long)bh * TT * HDIM;
    const float* Qg = g_scratch + 0ull * SZ;
    const float* Kg = g_scratch + 1ull * SZ;
    const float* Vg = g_scratch + 2ull * SZ;
    float*       Og = g_scratch + 3ull * SZ;

    const int tid  = threadIdx.x;
    const int lane = tid & 31;
    const int r0   = (tid >> 5) << 2;   // warp's first query row
    const int c2   = lane << 1;         // output cols c2, c2+1

    // Load Q tile (32x64), scalar
#pragma unroll
    for (int it = 0; it < 8; it++) {
        int idx = tid + it * 256;       // 0..2047
        int row = idx >> 6, col = idx & 63;
        Qs[row][col] = gld(Qg, base + (unsigned long long)(qt * 32 + row) * HDIM + col,
                           4ull * SZ);
    }

    float mrow[4], lrow[4], o[4][2];
#pragma unroll
    for (int i = 0; i < 4; i++) {
        mrow[i] = -1e30f; lrow[i] = 0.f;
        o[i][0] = 0.f;    o[i][1] = 0.f;
    }
    const float scale = 0.125f;   // 1/sqrt(64)

    for (int kt = 0; kt <= qt; kt++) {
        // Load K and V tiles (32x64 each), scalar
#pragma unroll
        for (int it = 0; it < 8; it++) {
            int idx = tid + it * 256;
            int row = idx >> 6, col = idx & 63;
            unsigned long long gidx =
                base + (unsigned long long)(kt * 32 + row) * HDIM + col;
            Ks[row][col] = gld(Kg, gidx, 4ull * SZ);
            Vs[row][col] = gld(Vg, gidx, 4ull * SZ);
        }
        __syncthreads();

        // S[i] = Q[r0+i] . K[lane]
        float s[4] = {0.f, 0.f, 0.f, 0.f};
#pragma unroll 8
        for (int d = 0; d < HDIM; d++) {
            float kd = Ks[lane][d];
#pragma unroll
            for (int i = 0; i < 4; i++) s[i] += Qs[r0 + i][d] * kd;
        }

        // scale + causal mask
        const int col = kt * 32 + lane;
        float mt[4];
#pragma unroll
        for (int i = 0; i < 4; i++) {
            int qg = qt * 32 + r0 + i;
            float sv = s[i] * scale;
            if (col > qg) sv = -1e30f;
            s[i] = sv;
            mt[i] = sv;
        }
#pragma unroll
        for (int off = 16; off > 0; off >>= 1)
#pragma unroll
            for (int i = 0; i < 4; i++)
                mt[i] = fmaxf(mt[i], __shfl_xor_sync(0xffffffffu, mt[i], off));

        float ps[4];
#pragma unroll
        for (int i = 0; i < 4; i++) {
            float mn   = fmaxf(mrow[i], mt[i]);
            float corr = __expf(mrow[i] - mn);
            mrow[i] = mn;
            float p = __expf(s[i] - mn);
            s[i]  = p;
            ps[i] = p;
            lrow[i] *= corr;
            o[i][0] *= corr;
            o[i][1] *= corr;
        }
#pragma unroll
        for (int off = 16; off > 0; off >>= 1)
#pragma unroll
            for (int i = 0; i < 4; i++)
                ps[i] += __shfl_xor_sync(0xffffffffu, ps[i], off);
#pragma unroll
        for (int i = 0; i < 4; i++) lrow[i] += ps[i];

        // Stash P (warp-private rows)
#pragma unroll
        for (int i = 0; i < 4; i++) Ps[r0 + i][lane] = s[i];
        __syncwarp();

        // O += P @ V
#pragma unroll 4
        for (int ss = 0; ss < 32; ss++) {
            float v0 = Vs[ss][c2];
            float v1 = Vs[ss][c2 + 1];
#pragma unroll
            for (int i = 0; i < 4; i++) {
                float p = Ps[r0 + i][ss];
                o[i][0] += p * v0;
                o[i][1] += p * v1;
            }
        }
        __syncthreads();
    }

    // Epilogue: normalize, write to scratch slot 3 in [B,T,H*HD]
#pragma unroll
    for (int i = 0; i < 4; i++) {
        float inv = 1.f / lrow[i];
        int tq = qt * 32 + r0 + i;
        unsigned long long off =
            (((unsigned long long)bb * TT + tq) * HH + h) * HDIM + c2;
        gst(Og, off,     (unsigned long long)SZ, o[i][0] * inv);
        gst(Og, off + 1, (unsigned long long)SZ, o[i][1] * inv);
    }
}

// ---------------------------------------------------------------------------
extern "C" void kernel_launch(void* const* d_in, const int* in_sizes, int n_in,
                              void* d_out, int out_size) {
    const float* x  = (const float*)d_in[0];
    const float* Wq = (const float*)d_in[1];
    const float* Wk = (const float*)d_in[2];
    const float* Wv = (const float*)d_in[3];
    const float* Wo = (const float*)d_in[4];
    const float* bo = (const float*)d_in[5];
    // Defensive size-based remap (element counts): x=4194304, bo=1024,
    // weights (in metadata order) = 1048576 each.
    if (n_in >= 6) {
        const float* big[8]; int nb = 0;
        const float* xx = 0; const float* bb = 0;
        for (int i = 0; i < n_in && i < 8; i++) {
            if (in_sizes[i] == BB * TT * DD)        xx = (const float*)d_in[i];
            else if (in_sizes[i] == DD)             bb = (const float*)d_in[i];
            else if (in_sizes[i] == DD * DD && nb < 8) big[nb++] = (const float*)d_in[i];
        }
        if (xx && bb && nb == 4) {
            x = xx; bo = bb;
            Wq = big[0]; Wk = big[1]; Wv = big[2]; Wo = big[3];
        }
    }
    float* out = (float*)d_out;
    (void)out_size;

    qkv_proj_kernel<<<dim3(MM / 128, NQ / 128, 3), 256>>>(x, Wq, Wk, Wv);
    attn_kernel<<<dim3(BB * HH, TT / 32), 256>>>();
    out_proj_kernel<<<dim3(MM / 128, DD / 128), 256>>>(Wo, bo, out);
}

// round 9
// speedup vs baseline: 1.3371x; 1.3371x over previous
#include <cuda_runtime.h>
#include <cstdint>

#define BB   2
#define TT   2048
#define DD   1024
#define HH   16
#define HDIM 64
#define MM   (BB*TT)          // 4096
#define NQ   (HH*HDIM)        // 1024
#define SZ   (BB*HH*TT*HDIM)  // 4,194,304

// One scratch array: [0]=q, [1]=k, [2]=v, [3]=attention output
__device__ __align__(256) float g_scratch[4ull * SZ];

// Clamped accessors (attention kernel, proven in R6)
__device__ __forceinline__ float gld(const float* __restrict__ p,
                                     unsigned long long i, unsigned long long n) {
    if (i >= n) i = n - 1;
    return p[i];
}
__device__ __forceinline__ void gst(float* __restrict__ p,
                                    unsigned long long i, unsigned long long n, float v) {
    if (i >= n) i = n - 1;
    p[i] = v;
}

// ======================= mma.sync tf32 helpers =============================
__device__ __forceinline__ void mma_tf32(float* d, const uint32_t* a,
                                         const uint32_t* b) {
    asm volatile(
        "mma.sync.aligned.m16n8k8.row.col.f32.tf32.tf32.f32 "
        "{%0,%1,%2,%3}, {%4,%5,%6,%7}, {%8,%9}, {%0,%1,%2,%3};"
        : "+f"(d[0]), "+f"(d[1]), "+f"(d[2]), "+f"(d[3])
        : "r"(a[0]), "r"(a[1]), "r"(a[2]), "r"(a[3]), "r"(b[0]), "r"(b[1]));
}
__device__ __forceinline__ float hi_part(float x) {
    return __uint_as_float(__float_as_uint(x) & 0xFFFFE000u);
}

// Shared GEMM smem: A[128][16] hi/lo (stride 20), B[16][128] hi/lo (stride 136)
#define ASTR 20
#define BSTR 136
struct GemmSmem {
    float Ah[128 * ASTR];
    float Al[128 * ASTR];
    float Bh[16 * BSTR];
    float Bl[16 * BSTR];
};

// Warp-level mma mainloop body (one K-chunk of 16, both hi/lo products).
// acc layout: acc[mt][nt][4]
__device__ __forceinline__ void mma_chunk(const GemmSmem& sm, int wid, int lane,
                                          float acc[4][4][4]) {
    const int warp_m = (wid >> 2) * 64;
    const int warp_n = (wid & 3) * 32;
    const int g  = lane >> 2;      // group id 0..7
    const int tg = lane & 3;       // thread in group 0..3
#pragma unroll
    for (int ks = 0; ks < 2; ks++) {
        const int kb = ks * 8;
        uint32_t ah[4][4], al[4][4];
#pragma unroll
        for (int mt = 0; mt < 4; mt++) {
            const int r0 = warp_m + mt * 16 + g;
            const int c0 = kb + tg;
            ah[mt][0] = __float_as_uint(sm.Ah[r0 * ASTR + c0]);
            ah[mt][1] = __float_as_uint(sm.Ah[(r0 + 8) * ASTR + c0]);
            ah[mt][2] = __float_as_uint(sm.Ah[r0 * ASTR + c0 + 4]);
            ah[mt][3] = __float_as_uint(sm.Ah[(r0 + 8) * ASTR + c0 + 4]);
            al[mt][0] = __float_as_uint(sm.Al[r0 * ASTR + c0]);
            al[mt][1] = __float_as_uint(sm.Al[(r0 + 8) * ASTR + c0]);
            al[mt][2] = __float_as_uint(sm.Al[r0 * ASTR + c0 + 4]);
            al[mt][3] = __float_as_uint(sm.Al[(r0 + 8) * ASTR + c0 + 4]);
        }
        uint32_t bh[4][2], bl[4][2];
#pragma unroll
        for (int nt = 0; nt < 4; nt++) {
            const int n0 = warp_n + nt * 8 + g;
            bh[nt][0] = __float_as_uint(sm.Bh[(kb + tg) * BSTR + n0]);
            bh[nt][1] = __float_as_uint(sm.Bh[(kb + 4 + tg) * BSTR + n0]);
            bl[nt][0] = __float_as_uint(sm.Bl[(kb + tg) * BSTR + n0]);
            bl[nt][1] = __float_as_uint(sm.Bl[(kb + 4 + tg) * BSTR + n0]);
        }
#pragma unroll
        for (int mt = 0; mt < 4; mt++)
#pragma unroll
            for (int nt = 0; nt < 4; nt++) {
                mma_tf32(acc[mt][nt], ah[mt], bh[nt]);
                mma_tf32(acc[mt][nt], ah[mt], bl[nt]);
                mma_tf32(acc[mt][nt], al[mt], bh[nt]);
            }
    }
}

// ---------------------------------------------------------------------------
// QKV projection (tensor): out[b,h,t,hd] = sum_d x[b,t,d] * W[h,d,hd]
// Grid (32, 8, 3), block 256 (8 warps; 2x4 warp grid; warp tile 64x32).
// ---------------------------------------------------------------------------
__global__ __launch_bounds__(256)
void qkv_mma_kernel(const float* __restrict__ x,
                    const float* __restrict__ Wq,
                    const float* __restrict__ Wk,
                    const float* __restrict__ Wv) {
    __shared__ GemmSmem sm;
    const float* W = (blockIdx.z == 0) ? Wq : (blockIdx.z == 1) ? Wk : Wv;
    float* out = g_scratch + (size_t)blockIdx.z * SZ;

    const int bm   = blockIdx.x * 128;
    const int bn   = blockIdx.y * 128;
    const int tid  = threadIdx.x;
    const int wid  = tid >> 5;
    const int lane = tid & 31;

    float acc[4][4][4];
#pragma unroll
    for (int mt = 0; mt < 4; mt++)
#pragma unroll
        for (int nt = 0; nt < 4; nt++)
#pragma unroll
            for (int r = 0; r < 4; r++) acc[mt][nt][r] = 0.f;

    for (int c = 0; c < 64; c++) {
        const int k0 = c * 16;
        // stage global loads (2 float4 each for A and B per thread)
        float4 av[2], bv[2];
        int arow[2], ac4[2], bk[2], bn4[2];
#pragma unroll
        for (int it = 0; it < 2; it++) {
            int idx = tid + it * 256;              // 0..511
            arow[it] = idx >> 2;
            ac4[it]  = (idx & 3) << 2;
            av[it] = *reinterpret_cast<const float4*>(
                &x[(size_t)(bm + arow[it]) * DD + k0 + ac4[it]]);
            bk[it]  = idx >> 5;                    // 0..15
            bn4[it] = (idx & 31) << 2;             // 0..124
            int n = bn + bn4[it];
            bv[it] = *reinterpret_cast<const float4*>(
                &W[((size_t)(n >> 6) * DD + (k0 + bk[it])) * HDIM + (n & 63)]);
        }
        if (c > 0) __syncthreads();   // all warps done reading smem of prev chunk
#pragma unroll
        for (int it = 0; it < 2; it++) {
            float4 h, l;
            h.x = hi_part(av[it].x); l.x = av[it].x - h.x;
            h.y = hi_part(av[it].y); l.y = av[it].y - h.y;
            h.z = hi_part(av[it].z); l.z = av[it].z - h.z;
            h.w = hi_part(av[it].w); l.w = av[it].w - h.w;
            *reinterpret_cast<float4*>(&sm.Ah[arow[it] * ASTR + ac4[it]]) = h;
            *reinterpret_cast<float4*>(&sm.Al[arow[it] * ASTR + ac4[it]]) = l;
            h.x = hi_part(bv[it].x); l.x = bv[it].x - h.x;
            h.y = hi_part(bv[it].y); l.y = bv[it].y - h.y;
            h.z = hi_part(bv[it].z); l.z = bv[it].z - h.z;
            h.w = hi_part(bv[it].w); l.w = bv[it].w - h.w;
            *reinterpret_cast<float4*>(&sm.Bh[bk[it] * BSTR + bn4[it]]) = h;
            *reinterpret_cast<float4*>(&sm.Bl[bk[it] * BSTR + bn4[it]]) = l;
        }
        __syncthreads();
        mma_chunk(sm, wid, lane, acc);
    }

    // Epilogue: acc -> g_scratch [B,H,T,HD]
    const int warp_m = (wid >> 2) * 64;
    const int warp_n = (wid & 3) * 32;
    const int g  = lane >> 2;
    const int tg = lane & 3;
#pragma unroll
    for (int mt = 0; mt < 4; mt++) {
#pragma unroll
        for (int nt = 0; nt < 4; nt++) {
#pragma unroll
            for (int r = 0; r < 4; r++) {
                int m = bm + warp_m + mt * 16 + g + ((r >= 2) ? 8 : 0);
                int n = bn + warp_n + nt * 8 + tg * 2 + (r & 1);
                int b = m >> 11, t = m & 2047;
                out[(((size_t)b * HH + (n >> 6)) * TT + t) * HDIM + (n & 63)] =
                    acc[mt][nt][r];
            }
        }
    }
}

// ---------------------------------------------------------------------------
// Output projection (tensor): out[m,n] = sum_d A[m,d]*Wo[d,n] + bo[n]
// Grid (32, 8), block 256.
// ---------------------------------------------------------------------------
__global__ __launch_bounds__(256)
void out_mma_kernel(const float* __restrict__ Wo,
                    const float* __restrict__ bo,
                    float* __restrict__ outp) {
    __shared__ GemmSmem sm;
    const float* A = g_scratch + 3ull * SZ;

    const int bm   = blockIdx.x * 128;
    const int bn   = blockIdx.y * 128;
    const int tid  = threadIdx.x;
    const int wid  = tid >> 5;
    const int lane = tid & 31;

    float acc[4][4][4];
#pragma unroll
    for (int mt = 0; mt < 4; mt++)
#pragma unroll
        for (int nt = 0; nt < 4; nt++)
#pragma unroll
            for (int r = 0; r < 4; r++) acc[mt][nt][r] = 0.f;

    for (int c = 0; c < 64; c++) {
        const int k0 = c * 16;
        float4 av[2], bv[2];
        int arow[2], ac4[2], bk[2], bn4[2];
#pragma unroll
        for (int it = 0; it < 2; it++) {
            int idx = tid + it * 256;
            arow[it] = idx >> 2;
            ac4[it]  = (idx & 3) << 2;
            av[it] = *reinterpret_cast<const float4*>(
                &A[(size_t)(bm + arow[it]) * DD + k0 + ac4[it]]);
            bk[it]  = idx >> 5;
            bn4[it] = (idx & 31) << 2;
            bv[it] = *reinterpret_cast<const float4*>(
                &Wo[(size_t)(k0 + bk[it]) * DD + bn + bn4[it]]);
        }
        if (c > 0) __syncthreads();
#pragma unroll
        for (int it = 0; it < 2; it++) {
            float4 h, l;
            h.x = hi_part(av[it].x); l.x = av[it].x - h.x;
            h.y = hi_part(av[it].y); l.y = av[it].y - h.y;
            h.z = hi_part(av[it].z); l.z = av[it].z - h.z;
            h.w = hi_part(av[it].w); l.w = av[it].w - h.w;
            *reinterpret_cast<float4*>(&sm.Ah[arow[it] * ASTR + ac4[it]]) = h;
            *reinterpret_cast<float4*>(&sm.Al[arow[it] * ASTR + ac4[it]]) = l;
            h.x = hi_part(bv[it].x); l.x = bv[it].x - h.x;
            h.y = hi_part(bv[it].y); l.y = bv[it].y - h.y;
            h.z = hi_part(bv[it].z); l.z = bv[it].z - h.z;
            h.w = hi_part(bv[it].w); l.w = bv[it].w - h.w;
            *reinterpret_cast<float4*>(&sm.Bh[bk[it] * BSTR + bn4[it]]) = h;
            *reinterpret_cast<float4*>(&sm.Bl[bk[it] * BSTR + bn4[it]]) = l;
        }
        __syncthreads();
        mma_chunk(sm, wid, lane, acc);
    }

    const int warp_m = (wid >> 2) * 64;
    const int warp_n = (wid & 3) * 32;
    const int g  = lane >> 2;
    const int tg = lane & 3;
#pragma unroll
    for (int mt = 0; mt < 4; mt++) {
#pragma unroll
        for (int nt = 0; nt < 4; nt++) {
#pragma unroll
            for (int r = 0; r < 4; r++) {
                int m = bm + warp_m + mt * 16 + g + ((r >= 2) ? 8 : 0);
                int n = bn + warp_n + nt * 8 + tg * 2 + (r & 1);
                outp[(size_t)m * DD + n] = acc[mt][nt][r] + bo[n];
            }
        }
    }
}

// ---------------------------------------------------------------------------
// Flash attention (causal), fp32, online softmax — unchanged from R6 (proven).
// Grid: (B*H, T/32). Block: 256 threads = 8 warps.
// ---------------------------------------------------------------------------
__global__ __launch_bounds__(256)
void attn_kernel() {
    __shared__ float Qs[32][65];
    __shared__ float Ks[32][65];
    __shared__ float Vs[32][66];
    __shared__ float Ps[32][33];

    const int bh = blockIdx.x;
    const int qt = blockIdx.y;
    const int bb = bh >> 4;
    const int h  = bh & 15;
    const unsigned long long base = (unsigned long long)bh * TT * HDIM;
    const float* Qg = g_scratch + 0ull * SZ;
    const float* Kg = g_scratch + 1ull * SZ;
    const float* Vg = g_scratch + 2ull * SZ;
    float*       Og = g_scratch + 3ull * SZ;

    const int tid  = threadIdx.x;
    const int lane = tid & 31;
    const int r0   = (tid >> 5) << 2;
    const int c2   = lane << 1;

#pragma unroll
    for (int it = 0; it < 8; it++) {
        int idx = tid + it * 256;
        int row = idx >> 6, col = idx & 63;
        Qs[row][col] = gld(Qg, base + (unsigned long long)(qt * 32 + row) * HDIM + col,
                           4ull * SZ);
    }

    float mrow[4], lrow[4], o[4][2];
#pragma unroll
    for (int i = 0; i < 4; i++) {
        mrow[i] = -1e30f; lrow[i] = 0.f;
        o[i][0] = 0.f;    o[i][1] = 0.f;
    }
    const float scale = 0.125f;

    for (int kt = 0; kt <= qt; kt++) {
#pragma unroll
        for (int it = 0; it < 8; it++) {
            int idx = tid + it * 256;
            int row = idx >> 6, col = idx & 63;
            unsigned long long gidx =
                base + (unsigned long long)(kt * 32 + row) * HDIM + col;
            Ks[row][col] = gld(Kg, gidx, 4ull * SZ);
            Vs[row][col] = gld(Vg, gidx, 4ull * SZ);
        }
        __syncthreads();

        float s[4] = {0.f, 0.f, 0.f, 0.f};
#pragma unroll 8
        for (int d = 0; d < HDIM; d++) {
            float kd = Ks[lane][d];
#pragma unroll
            for (int i = 0; i < 4; i++) s[i] += Qs[r0 + i][d] * kd;
        }

        const int col = kt * 32 + lane;
        float mt[4];
#pragma unroll
        for (int i = 0; i < 4; i++) {
            int qg = qt * 32 + r0 + i;
            float sv = s[i] * scale;
            if (col > qg) sv = -1e30f;
            s[i] = sv;
            mt[i] = sv;
        }
#pragma unroll
        for (int off = 16; off > 0; off >>= 1)
#pragma unroll
            for (int i = 0; i < 4; i++)
                mt[i] = fmaxf(mt[i], __shfl_xor_sync(0xffffffffu, mt[i], off));

        float ps[4];
#pragma unroll
        for (int i = 0; i < 4; i++) {
            float mn   = fmaxf(mrow[i], mt[i]);
            float corr = __expf(mrow[i] - mn);
            mrow[i] = mn;
            float p = __expf(s[i] - mn);
            s[i]  = p;
            ps[i] = p;
            lrow[i] *= corr;
            o[i][0] *= corr;
            o[i][1] *= corr;
        }
#pragma unroll
        for (int off = 16; off > 0; off >>= 1)
#pragma unroll
            for (int i = 0; i < 4; i++)
                ps[i] += __shfl_xor_sync(0xffffffffu, ps[i], off);
#pragma unroll
        for (int i = 0; i < 4; i++) lrow[i] += ps[i];

#pragma unroll
        for (int i = 0; i < 4; i++) Ps[r0 + i][lane] = s[i];
        __syncwarp();

#pragma unroll 4
        for (int ss = 0; ss < 32; ss++) {
            float v0 = Vs[ss][c2];
            float v1 = Vs[ss][c2 + 1];
#pragma unroll
            for (int i = 0; i < 4; i++) {
                float p = Ps[r0 + i][ss];
                o[i][0] += p * v0;
                o[i][1] += p * v1;
            }
        }
        __syncthreads();
    }

#pragma unroll
    for (int i = 0; i < 4; i++) {
        float inv = 1.f / lrow[i];
        int tq = qt * 32 + r0 + i;
        unsigned long long off =
            (((unsigned long long)bb * TT + tq) * HH + h) * HDIM + c2;
        gst(Og, off,     (unsigned long long)SZ, o[i][0] * inv);
        gst(Og, off + 1, (unsigned long long)SZ, o[i][1] * inv);
    }
}

// ---------------------------------------------------------------------------
extern "C" void kernel_launch(void* const* d_in, const int* in_sizes, int n_in,
                              void* d_out, int out_size) {
    const float* x  = (const float*)d_in[0];
    const float* Wq = (const float*)d_in[1];
    const float* Wk = (const float*)d_in[2];
    const float* Wv = (const float*)d_in[3];
    const float* Wo = (const float*)d_in[4];
    const float* bo = (const float*)d_in[5];
    if (n_in >= 6) {
        const float* big[8]; int nb = 0;
        const float* xx = 0; const float* bb = 0;
        for (int i = 0; i < n_in && i < 8; i++) {
            if (in_sizes[i] == BB * TT * DD)           xx = (const float*)d_in[i];
            else if (in_sizes[i] == DD)                bb = (const float*)d_in[i];
            else if (in_sizes[i] == DD * DD && nb < 8) big[nb++] = (const float*)d_in[i];
        }
        if (xx && bb && nb == 4) {
            x = xx; bo = bb;
            Wq = big[0]; Wk = big[1]; Wv = big[2]; Wo = big[3];
        }
    }
    float* out = (float*)d_out;
    (void)out_size;

    qkv_mma_kernel<<<dim3(MM / 128, NQ / 128, 3), 256>>>(x, Wq, Wk, Wv);
    attn_kernel<<<dim3(BB * HH, TT / 32), 256>>>();
    out_mma_kernel<<<dim3(MM / 128, DD / 128), 256>>>(Wo, bo, out);
}

// round 10
// speedup vs baseline: 2.2349x; 1.6715x over previous
#include <cuda_runtime.h>
#include <cstdint>

#define BB   2
#define TT   2048
#define DD   1024
#define HH   16
#define HDIM 64
#define MM   (BB*TT)          // 4096
#define NQ   (HH*HDIM)        // 1024
#define SZ   (BB*HH*TT*HDIM)  // 4,194,304

// One scratch array: [0]=q, [1]=k, [2]=v, [3]=attention output
__device__ __align__(256) float g_scratch[4ull * SZ];

// ======================= mma.sync tf32 helpers =============================
__device__ __forceinline__ void mma_tf32(float* d, const uint32_t* a,
                                         const uint32_t* b) {
    asm volatile(
        "mma.sync.aligned.m16n8k8.row.col.f32.tf32.tf32.f32 "
        "{%0,%1,%2,%3}, {%4,%5,%6,%7}, {%8,%9}, {%0,%1,%2,%3};"
        : "+f"(d[0]), "+f"(d[1]), "+f"(d[2]), "+f"(d[3])
        : "r"(a[0]), "r"(a[1]), "r"(a[2]), "r"(a[3]), "r"(b[0]), "r"(b[1]));
}
__device__ __forceinline__ float hi_part(float x) {
    return __uint_as_float(__float_as_uint(x) & 0xFFFFE000u);
}

// Shared GEMM smem: A[128][16] hi/lo (stride 20), B[16][128] hi/lo (stride 136)
#define ASTR 20
#define BSTR 136
struct GemmSmem {
    float Ah[128 * ASTR];
    float Al[128 * ASTR];
    float Bh[16 * BSTR];
    float Bl[16 * BSTR];
};

__device__ __forceinline__ void mma_chunk(const GemmSmem& sm, int wid, int lane,
                                          float acc[4][4][4]) {
    const int warp_m = (wid >> 2) * 64;
    const int warp_n = (wid & 3) * 32;
    const int g  = lane >> 2;
    const int tg = lane & 3;
#pragma unroll
    for (int ks = 0; ks < 2; ks++) {
        const int kb = ks * 8;
        uint32_t ah[4][4], al[4][4];
#pragma unroll
        for (int mt = 0; mt < 4; mt++) {
            const int r0 = warp_m + mt * 16 + g;
            const int c0 = kb + tg;
            ah[mt][0] = __float_as_uint(sm.Ah[r0 * ASTR + c0]);
            ah[mt][1] = __float_as_uint(sm.Ah[(r0 + 8) * ASTR + c0]);
            ah[mt][2] = __float_as_uint(sm.Ah[r0 * ASTR + c0 + 4]);
            ah[mt][3] = __float_as_uint(sm.Ah[(r0 + 8) * ASTR + c0 + 4]);
            al[mt][0] = __float_as_uint(sm.Al[r0 * ASTR + c0]);
            al[mt][1] = __float_as_uint(sm.Al[(r0 + 8) * ASTR + c0]);
            al[mt][2] = __float_as_uint(sm.Al[r0 * ASTR + c0 + 4]);
            al[mt][3] = __float_as_uint(sm.Al[(r0 + 8) * ASTR + c0 + 4]);
        }
        uint32_t bh[4][2], bl[4][2];
#pragma unroll
        for (int nt = 0; nt < 4; nt++) {
            const int n0 = warp_n + nt * 8 + g;
            bh[nt][0] = __float_as_uint(sm.Bh[(kb + tg) * BSTR + n0]);
            bh[nt][1] = __float_as_uint(sm.Bh[(kb + 4 + tg) * BSTR + n0]);
            bl[nt][0] = __float_as_uint(sm.Bl[(kb + tg) * BSTR + n0]);
            bl[nt][1] = __float_as_uint(sm.Bl[(kb + 4 + tg) * BSTR + n0]);
        }
#pragma unroll
        for (int mt = 0; mt < 4; mt++)
#pragma unroll
            for (int nt = 0; nt < 4; nt++) {
                mma_tf32(acc[mt][nt], ah[mt], bh[nt]);
                mma_tf32(acc[mt][nt], ah[mt], bl[nt]);
                mma_tf32(acc[mt][nt], al[mt], bh[nt]);
            }
    }
}

// ---------------------------------------------------------------------------
// QKV projection (tensor). Grid (32, 8, 3), block 256, 2 CTAs/SM.
// ---------------------------------------------------------------------------
__global__ __launch_bounds__(256, 2)
void qkv_mma_kernel(const float* __restrict__ x,
                    const float* __restrict__ Wq,
                    const float* __restrict__ Wk,
                    const float* __restrict__ Wv) {
    __shared__ GemmSmem sm;
    const float* W = (blockIdx.z == 0) ? Wq : (blockIdx.z == 1) ? Wk : Wv;
    float* out = g_scratch + (size_t)blockIdx.z * SZ;

    const int bm   = blockIdx.x * 128;
    const int bn   = blockIdx.y * 128;
    const int tid  = threadIdx.x;
    const int wid  = tid >> 5;
    const int lane = tid & 31;

    float acc[4][4][4];
#pragma unroll
    for (int mt = 0; mt < 4; mt++)
#pragma unroll
        for (int nt = 0; nt < 4; nt++)
#pragma unroll
            for (int r = 0; r < 4; r++) acc[mt][nt][r] = 0.f;

    for (int c = 0; c < 64; c++) {
        const int k0 = c * 16;
        float4 av[2], bv[2];
        int arow[2], ac4[2], bk[2], bn4[2];
#pragma unroll
        for (int it = 0; it < 2; it++) {
            int idx = tid + it * 256;
            arow[it] = idx >> 2;
            ac4[it]  = (idx & 3) << 2;
            av[it] = *reinterpret_cast<const float4*>(
                &x[(size_t)(bm + arow[it]) * DD + k0 + ac4[it]]);
            bk[it]  = idx >> 5;
            bn4[it] = (idx & 31) << 2;
            int n = bn + bn4[it];
            bv[it] = *reinterpret_cast<const float4*>(
                &W[((size_t)(n >> 6) * DD + (k0 + bk[it])) * HDIM + (n & 63)]);
        }
        if (c > 0) __syncthreads();
#pragma unroll
        for (int it = 0; it < 2; it++) {
            float4 h, l;
            h.x = hi_part(av[it].x); l.x = av[it].x - h.x;
            h.y = hi_part(av[it].y); l.y = av[it].y - h.y;
            h.z = hi_part(av[it].z); l.z = av[it].z - h.z;
            h.w = hi_part(av[it].w); l.w = av[it].w - h.w;
            *reinterpret_cast<float4*>(&sm.Ah[arow[it] * ASTR + ac4[it]]) = h;
            *reinterpret_cast<float4*>(&sm.Al[arow[it] * ASTR + ac4[it]]) = l;
            h.x = hi_part(bv[it].x); l.x = bv[it].x - h.x;
            h.y = hi_part(bv[it].y); l.y = bv[it].y - h.y;
            h.z = hi_part(bv[it].z); l.z = bv[it].z - h.z;
            h.w = hi_part(bv[it].w); l.w = bv[it].w - h.w;
            *reinterpret_cast<float4*>(&sm.Bh[bk[it] * BSTR + bn4[it]]) = h;
            *reinterpret_cast<float4*>(&sm.Bl[bk[it] * BSTR + bn4[it]]) = l;
        }
        __syncthreads();
        mma_chunk(sm, wid, lane, acc);
    }

    const int warp_m = (wid >> 2) * 64;
    const int warp_n = (wid & 3) * 32;
    const int g  = lane >> 2;
    const int tg = lane & 3;
#pragma unroll
    for (int mt = 0; mt < 4; mt++) {
#pragma unroll
        for (int nt = 0; nt < 4; nt++) {
#pragma unroll
            for (int r = 0; r < 4; r++) {
                int m = bm + warp_m + mt * 16 + g + ((r >= 2) ? 8 : 0);
                int n = bn + warp_n + nt * 8 + tg * 2 + (r & 1);
                int b = m >> 11, t = m & 2047;
                out[(((size_t)b * HH + (n >> 6)) * TT + t) * HDIM + (n & 63)] =
                    acc[mt][nt][r];
            }
        }
    }
}

// ---------------------------------------------------------------------------
// Output projection (tensor). Grid (32, 8), block 256, 2 CTAs/SM.
// ---------------------------------------------------------------------------
__global__ __launch_bounds__(256, 2)
void out_mma_kernel(const float* __restrict__ Wo,
                    const float* __restrict__ bo,
                    float* __restrict__ outp) {
    __shared__ GemmSmem sm;
    const float* A = g_scratch + 3ull * SZ;

    const int bm   = blockIdx.x * 128;
    const int bn   = blockIdx.y * 128;
    const int tid  = threadIdx.x;
    const int wid  = tid >> 5;
    const int lane = tid & 31;

    float acc[4][4][4];
#pragma unroll
    for (int mt = 0; mt < 4; mt++)
#pragma unroll
        for (int nt = 0; nt < 4; nt++)
#pragma unroll
            for (int r = 0; r < 4; r++) acc[mt][nt][r] = 0.f;

    for (int c = 0; c < 64; c++) {
        const int k0 = c * 16;
        float4 av[2], bv[2];
        int arow[2], ac4[2], bk[2], bn4[2];
#pragma unroll
        for (int it = 0; it < 2; it++) {
            int idx = tid + it * 256;
            arow[it] = idx >> 2;
            ac4[it]  = (idx & 3) << 2;
            av[it] = *reinterpret_cast<const float4*>(
                &A[(size_t)(bm + arow[it]) * DD + k0 + ac4[it]]);
            bk[it]  = idx >> 5;
            bn4[it] = (idx & 31) << 2;
            bv[it] = *reinterpret_cast<const float4*>(
                &Wo[(size_t)(k0 + bk[it]) * DD + bn + bn4[it]]);
        }
        if (c > 0) __syncthreads();
#pragma unroll
        for (int it = 0; it < 2; it++) {
            float4 h, l;
            h.x = hi_part(av[it].x); l.x = av[it].x - h.x;
            h.y = hi_part(av[it].y); l.y = av[it].y - h.y;
            h.z = hi_part(av[it].z); l.z = av[it].z - h.z;
            h.w = hi_part(av[it].w); l.w = av[it].w - h.w;
            *reinterpret_cast<float4*>(&sm.Ah[arow[it] * ASTR + ac4[it]]) = h;
            *reinterpret_cast<float4*>(&sm.Al[arow[it] * ASTR + ac4[it]]) = l;
            h.x = hi_part(bv[it].x); l.x = bv[it].x - h.x;
            h.y = hi_part(bv[it].y); l.y = bv[it].y - h.y;
            h.z = hi_part(bv[it].z); l.z = bv[it].z - h.z;
            h.w = hi_part(bv[it].w); l.w = bv[it].w - h.w;
            *reinterpret_cast<float4*>(&sm.Bh[bk[it] * BSTR + bn4[it]]) = h;
            *reinterpret_cast<float4*>(&sm.Bl[bk[it] * BSTR + bn4[it]]) = l;
        }
        __syncthreads();
        mma_chunk(sm, wid, lane, acc);
    }

    const int warp_m = (wid >> 2) * 64;
    const int warp_n = (wid & 3) * 32;
    const int g  = lane >> 2;
    const int tg = lane & 3;
#pragma unroll
    for (int mt = 0; mt < 4; mt++) {
#pragma unroll
        for (int nt = 0; nt < 4; nt++) {
#pragma unroll
            for (int r = 0; r < 4; r++) {
                int m = bm + warp_m + mt * 16 + g + ((r >= 2) ? 8 : 0);
                int n = bn + warp_n + nt * 8 + tg * 2 + (r & 1);
                outp[(size_t)m * DD + n] = acc[mt][nt][r] + bo[n];
            }
        }
    }
}

// ---------------------------------------------------------------------------
// Tensor-core flash attention (causal), split-tf32, online softmax.
// Grid: (B*H, T/64). Block: 128 threads = 4 warps; warp owns 16 query rows.
// K/V tiles of 32 keys. Q held in registers as pre-split tf32 fragments.
// Smem: union{Kh|Kl , Ph|Pl} + Vh|Vl = 36.9 KB static.
// ---------------------------------------------------------------------------
#define KSTR 68   // K smem stride (words)
#define VSTR 72   // V smem stride
#define PSTR 36   // P smem stride

__global__ __launch_bounds__(128)
void attn_mma_kernel() {
    __shared__ float sU[4608];          // Kh[32*68]=2176 | Kl -> 4352 ; Ph[64*36]=2304 | Pl -> 4608
    __shared__ float sVh[32 * VSTR];    // 2304
    __shared__ float sVl[32 * VSTR];

    float* Kh = sU;
    float* Kl = sU + 32 * KSTR;
    float* Ph = sU;
    float* Pl = sU + 64 * PSTR;

    const int bh = blockIdx.x;          // b*H + h
    const int qt = blockIdx.y;          // 64-query tile
    const int bb = bh >> 4;
    const int h  = bh & 15;
    const size_t base = (size_t)bh * TT * HDIM;
    const float* Qg = g_scratch + 0ull * SZ + base;
    const float* Kg = g_scratch + 1ull * SZ + base;
    const float* Vg = g_scratch + 2ull * SZ + base;
    float*       Og = g_scratch + 3ull * SZ;

    const int tid  = threadIdx.x;
    const int wid  = tid >> 5;
    const int lane = tid & 31;
    const int g    = lane >> 2;
    const int tg   = lane & 3;
    const int wr   = wid * 16;          // warp's row base within q-tile
    const int qrow0 = qt * 64 + wr + g;
    const int qrow1 = qrow0 + 8;

    // ---- load Q fragments (pre-split hi/lo) ----
    uint32_t qh[8][4], ql[8][4];
#pragma unroll
    for (int ks = 0; ks < 8; ks++) {
        const int kb = ks * 8;
#pragma unroll
        for (int r = 0; r < 4; r++) {
            int row = (r & 1) ? qrow1 : qrow0;
            int col = kb + tg + ((r >= 2) ? 4 : 0);
            float v = __ldg(&Qg[(size_t)row * HDIM + col]);
            float hv = hi_part(v);
            qh[ks][r] = __float_as_uint(hv);
            ql[ks][r] = __float_as_uint(v - hv);
        }
    }
    // reorder to a0..a3 = {r0c0, r1c0, r0c4, r1c4}: loaded r index: 0->(q0,c0)
    // 1->(q1,c0) 2->(q0,c4) 3->(q1,c4)  — already matches a-frag order.

    float oacc[8][4];
#pragma unroll
    for (int nt = 0; nt < 8; nt++)
#pragma unroll
        for (int r = 0; r < 4; r++) oacc[nt][r] = 0.f;
    float mrow0 = -1e30f, mrow1 = -1e30f, lrow0 = 0.f, lrow1 = 0.f;
    const float scale = 0.125f;

    const int kt_max = 2 * qt + 1;
    for (int kt = 0; kt <= kt_max; kt++) {
        __syncthreads();   // prev iter's P/V reads done before overwrite
        // ---- load K/V tile (32x64 each), split hi/lo ----
#pragma unroll
        for (int it = 0; it < 4; it++) {
            int idx = tid + it * 128;            // 0..511 float4 slots
            int row = idx >> 4, c4 = (idx & 15) << 2;
            float4 kv = *reinterpret_cast<const float4*>(
                &Kg[(size_t)(kt * 32 + row) * HDIM + c4]);
            float4 h4, l4;
            h4.x = hi_part(kv.x); l4.x = kv.x - h4.x;
            h4.y = hi_part(kv.y); l4.y = kv.y - h4.y;
            h4.z = hi_part(kv.z); l4.z = kv.z - h4.z;
            h4.w = hi_part(kv.w); l4.w = kv.w - h4.w;
            *reinterpret_cast<float4*>(&Kh[row * KSTR + c4]) = h4;
            *reinterpret_cast<float4*>(&Kl[row * KSTR + c4]) = l4;
            float4 vv = *reinterpret_cast<const float4*>(
                &Vg[(size_t)(kt * 32 + row) * HDIM + c4]);
            h4.x = hi_part(vv.x); l4.x = vv.x - h4.x;
            h4.y = hi_part(vv.y); l4.y = vv.y - h4.y;
            h4.z = hi_part(vv.z); l4.z = vv.z - h4.z;
            h4.w = hi_part(vv.w); l4.w = vv.w - h4.w;
            *reinterpret_cast<float4*>(&sVh[row * VSTR + c4]) = h4;
            *reinterpret_cast<float4*>(&sVl[row * VSTR + c4]) = l4;
        }
        __syncthreads();

        // ---- S = Q K^T (warp: 16 rows x 32 cols; nt=4) ----
        float sacc[4][4];
#pragma unroll
        for (int nt = 0; nt < 4; nt++)
#pragma unroll
            for (int r = 0; r < 4; r++) sacc[nt][r] = 0.f;
#pragma unroll
        for (int ks = 0; ks < 8; ks++) {
            const int kb = ks * 8;
#pragma unroll
            for (int nt = 0; nt < 4; nt++) {
                const int n0 = nt * 8 + g;
                uint32_t bhf[2], blf[2];
                bhf[0] = __float_as_uint(Kh[n0 * KSTR + kb + tg]);
                bhf[1] = __float_as_uint(Kh[n0 * KSTR + kb + tg + 4]);
                blf[0] = __float_as_uint(Kl[n0 * KSTR + kb + tg]);
                blf[1] = __float_as_uint(Kl[n0 * KSTR + kb + tg + 4]);
                mma_tf32(sacc[nt], qh[ks], bhf);
                mma_tf32(sacc[nt], qh[ks], blf);
                mma_tf32(sacc[nt], ql[ks], bhf);
            }
        }

        // ---- scale + causal mask + online softmax ----
        float mt0 = -1e30f, mt1 = -1e30f;
#pragma unroll
        for (int nt = 0; nt < 4; nt++) {
#pragma unroll
            for (int j = 0; j < 2; j++) {
                int scol = kt * 32 + nt * 8 + 2 * tg + j;
                float sv0 = sacc[nt][j] * scale;
                if (scol > qrow0) sv0 = -1e30f;
                sacc[nt][j] = sv0;
                mt0 = fmaxf(mt0, sv0);
                float sv1 = sacc[nt][2 + j] * scale;
                if (scol > qrow1) sv1 = -1e30f;
                sacc[nt][2 + j] = sv1;
                mt1 = fmaxf(mt1, sv1);
            }
        }
        // quad reduce (lanes sharing a row differ in tg = bits 0,1)
        mt0 = fmaxf(mt0, __shfl_xor_sync(0xffffffffu, mt0, 1));
        mt0 = fmaxf(mt0, __shfl_xor_sync(0xffffffffu, mt0, 2));
        mt1 = fmaxf(mt1, __shfl_xor_sync(0xffffffffu, mt1, 1));
        mt1 = fmaxf(mt1, __shfl_xor_sync(0xffffffffu, mt1, 2));

        float mn0 = fmaxf(mrow0, mt0), mn1 = fmaxf(mrow1, mt1);
        float corr0 = __expf(mrow0 - mn0), corr1 = __expf(mrow1 - mn1);
        mrow0 = mn0; mrow1 = mn1;
        float sum0 = 0.f, sum1 = 0.f;
#pragma unroll
        for (int nt = 0; nt < 4; nt++) {
#pragma unroll
            for (int j = 0; j < 2; j++) {
                float p0 = __expf(sacc[nt][j] - mn0);
                sacc[nt][j] = p0; sum0 += p0;
                float p1 = __expf(sacc[nt][2 + j] - mn1);
                sacc[nt][2 + j] = p1; sum1 += p1;
            }
        }
        sum0 += __shfl_xor_sync(0xffffffffu, sum0, 1);
        sum0 += __shfl_xor_sync(0xffffffffu, sum0, 2);
        sum1 += __shfl_xor_sync(0xffffffffu, sum1, 1);
        sum1 += __shfl_xor_sync(0xffffffffu, sum1, 2);
        lrow0 = lrow0 * corr0 + sum0;
        lrow1 = lrow1 * corr1 + sum1;
#pragma unroll
        for (int nt = 0; nt < 8; nt++) {
            oacc[nt][0] *= corr0; oacc[nt][1] *= corr0;
            oacc[nt][2] *= corr1; oacc[nt][3] *= corr1;
        }

        __syncthreads();   // all warps done reading K before P overwrites it

        // ---- write P hi/lo (warp-private rows) ----
#pragma unroll
        for (int nt = 0; nt < 4; nt++) {
            const int c0 = nt * 8 + 2 * tg;
            float p;
            p = sacc[nt][0];
            Ph[(wr + g) * PSTR + c0]     = hi_part(p);
            Pl[(wr + g) * PSTR + c0]     = p - hi_part(p);
            p = sacc[nt][1];
            Ph[(wr + g) * PSTR + c0 + 1] = hi_part(p);
            Pl[(wr + g) * PSTR + c0 + 1] = p - hi_part(p);
            p = sacc[nt][2];
            Ph[(wr + g + 8) * PSTR + c0]     = hi_part(p);
            Pl[(wr + g + 8) * PSTR + c0]     = p - hi_part(p);
            p = sacc[nt][3];
            Ph[(wr + g + 8) * PSTR + c0 + 1] = hi_part(p);
            Pl[(wr + g + 8) * PSTR + c0 + 1] = p - hi_part(p);
        }
        __syncwarp();

        // ---- O += P @ V (warp: 16 rows x 64 cols; nt=8, k=32) ----
#pragma unroll
        for (int ks = 0; ks < 4; ks++) {
            const int kb = ks * 8;
            uint32_t pa[4], pb[4];
            pa[0] = __float_as_uint(Ph[(wr + g) * PSTR + kb + tg]);
            pa[1] = __float_as_uint(Ph[(wr + g + 8) * PSTR + kb + tg]);
            pa[2] = __float_as_uint(Ph[(wr + g) * PSTR + kb + tg + 4]);
            pa[3] = __float_as_uint(Ph[(wr + g + 8) * PSTR + kb + tg + 4]);
            pb[0] = __float_as_uint(Pl[(wr + g) * PSTR + kb + tg]);
            pb[1] = __float_as_uint(Pl[(wr + g + 8) * PSTR + kb + tg]);
            pb[2] = __float_as_uint(Pl[(wr + g) * PSTR + kb + tg + 4]);
            pb[3] = __float_as_uint(Pl[(wr + g + 8) * PSTR + kb + tg + 4]);
#pragma unroll
            for (int nt = 0; nt < 8; nt++) {
                const int n0 = nt * 8 + g;
                uint32_t vh[2], vl[2];
                vh[0] = __float_as_uint(sVh[(kb + tg) * VSTR + n0]);
                vh[1] = __float_as_uint(sVh[(kb + 4 + tg) * VSTR + n0]);
                vl[0] = __float_as_uint(sVl[(kb + tg) * VSTR + n0]);
                vl[1] = __float_as_uint(sVl[(kb + 4 + tg) * VSTR + n0]);
                mma_tf32(oacc[nt], pa, vh);
                mma_tf32(oacc[nt], pa, vl);
                mma_tf32(oacc[nt], pb, vh);
            }
        }
    }

    // ---- epilogue: normalize, write [B,T,H*HD] ----
    const float inv0 = 1.f / lrow0;
    const float inv1 = 1.f / lrow1;
    const size_t ob0 = ((size_t)bb * TT + qrow0) * (HH * HDIM) + h * HDIM;
    const size_t ob1 = ((size_t)bb * TT + qrow1) * (HH * HDIM) + h * HDIM;
#pragma unroll
    for (int nt = 0; nt < 8; nt++) {
        const int c0 = nt * 8 + 2 * tg;
        Og[ob0 + c0]     = oacc[nt][0] * inv0;
        Og[ob0 + c0 + 1] = oacc[nt][1] * inv0;
        Og[ob1 + c0]     = oacc[nt][2] * inv1;
        Og[ob1 + c0 + 1] = oacc[nt][3] * inv1;
    }
}

// ---------------------------------------------------------------------------
extern "C" void kernel_launch(void* const* d_in, const int* in_sizes, int n_in,
                              void* d_out, int out_size) {
    const float* x  = (const float*)d_in[0];
    const float* Wq = (const float*)d_in[1];
    const float* Wk = (const float*)d_in[2];
    const float* Wv = (const float*)d_in[3];
    const float* Wo = (const float*)d_in[4];
    const float* bo = (const float*)d_in[5];
    if (n_in >= 6) {
        const float* big[8]; int nb = 0;
        const float* xx = 0; const float* bb = 0;
        for (int i = 0; i < n_in && i < 8; i++) {
            if (in_sizes[i] == BB * TT * DD)           xx = (const float*)d_in[i];
            else if (in_sizes[i] == DD)                bb = (const float*)d_in[i];
            else if (in_sizes[i] == DD * DD && nb < 8) big[nb++] = (const float*)d_in[i];
        }
        if (xx && bb && nb == 4) {
            x = xx; bo = bb;
            Wq = big[0]; Wk = big[1]; Wv = big[2]; Wo = big[3];
        }
    }
    float* out = (float*)d_out;
    (void)out_size;

    qkv_mma_kernel<<<dim3(MM / 128, NQ / 128, 3), 256>>>(x, Wq, Wk, Wv);
    attn_mma_kernel<<<dim3(BB * HH, TT / 64), 128>>>();
    out_mma_kernel<<<dim3(MM / 128, DD / 128), 256>>>(Wo, bo, out);
}